// round 2
// baseline (speedup 1.0000x reference)
#include <cuda_runtime.h>
#include <cstdint>
#include <cstddef>

// PHMLinear factored kernel.
// out[row, o*8+c] = sum_{e,r,a,i} x[row, a*128+i] * Wrl[e,i,r] * Wrr[e,r,o] * Wleft[e,a,c]
// Stages per row (one warp per row, lane == er = e*4+r for phases A/B):
//   A: y1[a,er] = sum_i x[a,i] * Wrl[e,i,r]        (y1 stays in the owning lane's registers)
//   B: u[er,c]  = sum_a y1[a,er] * Wleft[e,a,c]    (written packed to smem, 1KB per warp)
//   C: out[o,c] = sum_er u[er,c] * Wrr[e,r,o]      (lane owns o in {lane, lane+32, lane+64, lane+96})
// All hot loops use packed fma.rn.f32x2.

#define INDIM 1024
#define OUTDIM 1024

__device__ __forceinline__ unsigned long long pack2(float lo, float hi) {
    unsigned long long r;
    asm("mov.b64 %0, {%1, %2};" : "=l"(r) : "f"(lo), "f"(hi));
    return r;
}
__device__ __forceinline__ void unpack2(unsigned long long v, float &lo, float &hi) {
    asm("mov.b64 {%0, %1}, %2;" : "=f"(lo), "=f"(hi) : "l"(v));
}
__device__ __forceinline__ void fma2(unsigned long long &d, unsigned long long a, unsigned long long b) {
    asm("fma.rn.f32x2 %0, %1, %2, %0;" : "+l"(d) : "l"(a), "l"(b));
}

__global__ void __launch_bounds__(128, 4)
phm_kernel(const float* __restrict__ x,
           const float* __restrict__ wrl,   // [8][128][4]
           const float* __restrict__ wrr,   // [8][4][128] == [er][128]
           const float* __restrict__ wlf,   // [8][8][8]
           float* __restrict__ out,
           int nrows)
{
    // Padded layouts, all conflict-free for their access patterns (checked per
    // quarter-warp phase grouping for the LDS.128s).
    __shared__ float s_wrlT[32 * 132];               // [er][i], row pad 132
    __shared__ float s_wrr [32 * 128];               // [er][o], direct copy
    __shared__ float s_wl  [8 * 68];                 // [e][a*8+c], row pad 68 (16B aligned)
    __shared__ unsigned long long s_u2[4 * 4 * 32];  // per warp: [cp][er] packed {u[2cp],u[2cp+1]}

    const int tid  = threadIdx.x;
    const int lane = tid & 31;
    const int wid  = tid >> 5;

    // ---- stage weights (once per block) ----
    {
        const float4* s4 = (const float4*)wrr;
        float4* d4 = (float4*)s_wrr;
        #pragma unroll
        for (int k = 0; k < 8; k++) d4[tid + 128 * k] = s4[tid + 128 * k];
    }
    #pragma unroll
    for (int k = 0; k < 32; k++) {
        int idx = tid + 128 * k;                 // 4096 elements
        int er = idx >> 7, i = idx & 127;
        s_wrlT[er * 132 + i] = wrl[(er >> 2) * 512 + i * 4 + (er & 3)];
    }
    #pragma unroll
    for (int k = 0; k < 4; k++) {
        int idx = tid + 128 * k;                 // 512 elements
        s_wl[(idx >> 6) * 68 + (idx & 63)] = wlf[idx];
    }
    __syncthreads();

    const int e = lane >> 2;
    unsigned long long* u2 = s_u2 + (wid << 7);

    #pragma unroll 1
    for (int rit = 0; rit < 2; rit++) {
        int row = (blockIdx.x << 3) + (wid << 1) + rit;
        if (row >= nrows) break;
        const float* xg = x + (size_t)row * INDIM;

        // ---- Phase A: y1[a] for this lane's er. Packed acc: lo=even-i, hi=odd-i ----
        unsigned long long acc2[8];
        #pragma unroll
        for (int a = 0; a < 8; a++) acc2[a] = 0ull;

        const ulonglong2* wrow = (const ulonglong2*)(s_wrlT + lane * 132);
        #pragma unroll 4
        for (int i4 = 0; i4 < 32; i4++) {
            ulonglong2 wv = wrow[i4];  // {w[i],w[i+1]},{w[i+2],w[i+3]} for er=lane
            #pragma unroll
            for (int a = 0; a < 8; a++) {
                // broadcast load: every lane reads the same 16B (L1 dedups)
                ulonglong2 xv = *(const ulonglong2*)(xg + a * 128 + i4 * 4);
                fma2(acc2[a], xv.x, wv.x);
                fma2(acc2[a], xv.y, wv.y);
            }
        }

        // ---- Phase B: u[er,c] = sum_a y1[a] * Wleft[e,a,c] ----
        float uc[8];
        #pragma unroll
        for (int c = 0; c < 8; c++) uc[c] = 0.0f;
        #pragma unroll
        for (int a = 0; a < 8; a++) {
            float lo, hi;
            unpack2(acc2[a], lo, hi);
            float yv = lo + hi;
            const float* wla = s_wl + e * 68 + a * 8;
            float4 w0 = *(const float4*)(wla);
            float4 w1 = *(const float4*)(wla + 4);
            uc[0] += yv * w0.x; uc[1] += yv * w0.y; uc[2] += yv * w0.z; uc[3] += yv * w0.w;
            uc[4] += yv * w1.x; uc[5] += yv * w1.y; uc[6] += yv * w1.z; uc[7] += yv * w1.w;
        }
        #pragma unroll
        for (int cp = 0; cp < 4; cp++)
            u2[cp * 32 + lane] = pack2(uc[2 * cp], uc[2 * cp + 1]);
        __syncwarp();

        // ---- Phase C: out[o,c] = sum_er u[er,c] * Wrr[er,o] ----
        unsigned long long acc[16];  // [oi][cp]
        #pragma unroll
        for (int k = 0; k < 16; k++) acc[k] = 0ull;

        #pragma unroll 2
        for (int er = 0; er < 32; er++) {
            unsigned long long uv0 = u2[er];        // broadcast LDS.64 x4
            unsigned long long uv1 = u2[32 + er];
            unsigned long long uv2 = u2[64 + er];
            unsigned long long uv3 = u2[96 + er];
            const float* wr = s_wrr + er * 128 + lane;
            #pragma unroll
            for (int oi = 0; oi < 4; oi++) {
                float wvf = wr[oi * 32];
                unsigned long long wd = pack2(wvf, wvf);
                fma2(acc[oi * 4 + 0], wd, uv0);
                fma2(acc[oi * 4 + 1], wd, uv1);
                fma2(acc[oi * 4 + 2], wd, uv2);
                fma2(acc[oi * 4 + 3], wd, uv3);
            }
        }

        float* og = out + (size_t)row * OUTDIM;
        #pragma unroll
        for (int oi = 0; oi < 4; oi++) {
            int o = lane + oi * 32;
            ulonglong2 v0; v0.x = acc[oi * 4 + 0]; v0.y = acc[oi * 4 + 1];
            ulonglong2 v1; v1.x = acc[oi * 4 + 2]; v1.y = acc[oi * 4 + 3];
            *(ulonglong2*)(og + o * 8)     = v0;  // out[o, 0..3]
            *(ulonglong2*)(og + o * 8 + 4) = v1;  // out[o, 4..7]
        }
        __syncwarp();  // u2 reuse fence for next row
    }
}

extern "C" void kernel_launch(void* const* d_in, const int* in_sizes, int n_in,
                              void* d_out, int out_size) {
    const float* x   = (const float*)d_in[0];
    const float* wrl = (const float*)d_in[1];
    const float* wrr = (const float*)d_in[2];
    const float* wlf = (const float*)d_in[3];
    float* out = (float*)d_out;

    int nrows = in_sizes[0] / INDIM;   // B*S = 8192
    int grid = (nrows + 7) / 8;        // 8 rows per block (4 warps x 2 rows)
    phm_kernel<<<grid, 128>>>(x, wrl, wrr, wlf, out, nrows);
}

// round 4
// speedup vs baseline: 1.2269x; 1.2269x over previous
#include <cuda_runtime.h>
#include <cstdint>
#include <cstddef>

#define INDIM 1024
#define OUTDIM 1024

// Packed Wrr: g_wrr2[er*128 + lane*4 + oi] = wrr[er*128 + oi*32 + lane]
__device__ float g_wrr2[32 * 128];

__global__ void phm_prep(const float* __restrict__ wrr) {
    int idx = blockIdx.x * blockDim.x + threadIdx.x;
    if (idx < 4096) {
        int er = idx >> 7, t = idx & 127;
        int l = t >> 2, oi = t & 3;
        g_wrr2[idx] = wrr[er * 128 + oi * 32 + l];
    }
}

__device__ __forceinline__ unsigned long long pack2(float lo, float hi) {
    unsigned long long r;
    asm("mov.b64 %0, {%1, %2};" : "=l"(r) : "f"(lo), "f"(hi));
    return r;
}
__device__ __forceinline__ void unpack2(unsigned long long v, float &lo, float &hi) {
    asm("mov.b64 {%0, %1}, %2;" : "=f"(lo), "=f"(hi) : "l"(v));
}
__device__ __forceinline__ void fma2(unsigned long long &d, unsigned long long a, unsigned long long b) {
    asm("fma.rn.f32x2 %0, %1, %2, %0;" : "+l"(d) : "l"(a), "l"(b));
}

__global__ void __launch_bounds__(128, 4)
phm_main(const float* __restrict__ x,
         const float* __restrict__ wrl,   // [8][128][4]
         const float* __restrict__ wlf,   // [8][8][8]
         float* __restrict__ out,
         int nrows)
{
    // s_wrl2[p][i4][r][j]: p-stride 516 floats -> lanes p=0..7 hit distinct bank
    // quads for any fixed (i4,r) read (516 mod 32 = 4), 1 phase per quarter-warp.
    __shared__ __align__(16) float s_wrl2[8 * 516];
    __shared__ __align__(16) float s_wl[8 * 68];                 // [e][a*8+c], pad 68
    __shared__ __align__(16) unsigned long long s_u[4][4][4][34];// [warp][q][cp][er+pad]
    __shared__ __align__(16) float s_x[4][2][4 * 36];            // [warp][buf][q*36 + a*4]

    const int tid  = threadIdx.x;
    const int lane = tid & 31;
    const int wid  = tid >> 5;
    const int q = lane >> 3;   // row within warp tile
    const int p = lane & 7;    // er quartet (== e); r = 0..3 within

    // ---- stage weights (once per block) ----
    #pragma unroll
    for (int k = 0; k < 32; k++) {
        int idx = tid + 128 * k;                  // 4096
        int pp = idx >> 9;                        // e
        int rem = idx & 511;
        int i = rem >> 2, r = rem & 3;
        s_wrl2[pp * 516 + (i >> 2) * 16 + r * 4 + (i & 3)] = wrl[idx];
    }
    #pragma unroll
    for (int k = 0; k < 4; k++) {
        int idx = tid + 128 * k;                  // 512
        s_wl[(idx >> 6) * 68 + (idx & 63)] = wlf[idx];
    }
    __syncthreads();

    int row0 = blockIdx.x * 16 + wid * 4;
    if (row0 >= nrows) return;

    // loader role: lane (q,p) loads row q, a = p, 16B per slice
    const float* xld = x + (size_t)min(row0 + q, nrows - 1) * INDIM + p * 128;
    float* sxw0 = &s_x[wid][0][0];
    float* sxw1 = &s_x[wid][1][0];
    const int sx_off = q * 36 + p * 4;

    // ---- Phase A: acc[a][r] packed over i-parity ----
    unsigned long long acc[32];
    #pragma unroll
    for (int k = 0; k < 32; k++) acc[k] = 0ull;

    {   // prologue: slice0 -> buf0
        float4 t0 = *(const float4*)(xld);
        *(float4*)(sxw0 + sx_off) = t0;
    }
    float4 xq0 = *(const float4*)(xld + 4);   // slice 1
    float4 xq1 = *(const float4*)(xld + 8);   // slice 2

    const float* wvb = s_wrl2 + p * 516;
    const float* sxr = &s_x[wid][0][0] + q * 36;   // buf stride 144 floats

    #pragma unroll 2
    for (int i4 = 0; i4 < 32; i4++) {
        __syncwarp();
        if (i4 < 31) {
            // STS slice i4+1 into buf (i4+1)&1
            *(float4*)(((i4 & 1) ? sxw0 : sxw1) + sx_off) = xq0;
            xq0 = xq1;
            int nxt = (i4 + 3 <= 31) ? (i4 + 3) : 31;
            xq1 = *(const float4*)(xld + nxt * 4);
        }
        const float* xb = sxr + (i4 & 1) * 144;
        ulonglong2 wv0 = *(const ulonglong2*)(wvb + i4 * 16);
        ulonglong2 wv1 = *(const ulonglong2*)(wvb + i4 * 16 + 4);
        ulonglong2 wv2 = *(const ulonglong2*)(wvb + i4 * 16 + 8);
        ulonglong2 wv3 = *(const ulonglong2*)(wvb + i4 * 16 + 12);
        #pragma unroll
        for (int a = 0; a < 8; a++) {
            ulonglong2 xv = *(const ulonglong2*)(xb + a * 4);   // 1 phase, 4 rows served
            fma2(acc[a*4+0], xv.x, wv0.x); fma2(acc[a*4+0], xv.y, wv0.y);
            fma2(acc[a*4+1], xv.x, wv1.x); fma2(acc[a*4+1], xv.y, wv1.y);
            fma2(acc[a*4+2], xv.x, wv2.x); fma2(acc[a*4+2], xv.y, wv2.y);
            fma2(acc[a*4+3], xv.x, wv3.x); fma2(acc[a*4+3], xv.y, wv3.y);
        }
    }

    // ---- Phase B: u[r][cp] = sum_a y1[a][r] * Wl[p][a][c] (all in-lane) ----
    unsigned long long uc[16];
    #pragma unroll
    for (int k = 0; k < 16; k++) uc[k] = 0ull;
    const float* wlb = s_wl + p * 68;
    #pragma unroll
    for (int a = 0; a < 8; a++) {
        ulonglong2 W01 = *(const ulonglong2*)(wlb + a * 8);
        ulonglong2 W23 = *(const ulonglong2*)(wlb + a * 8 + 4);
        #pragma unroll
        for (int r = 0; r < 4; r++) {
            float lo, hi; unpack2(acc[a*4+r], lo, hi);
            float y = lo + hi;
            unsigned long long yd = pack2(y, y);
            fma2(uc[r*4+0], yd, W01.x);
            fma2(uc[r*4+1], yd, W01.y);
            fma2(uc[r*4+2], yd, W23.x);
            fma2(uc[r*4+3], yd, W23.y);
        }
    }
    #pragma unroll
    for (int r = 0; r < 4; r++)
        #pragma unroll
        for (int cp = 0; cp < 4; cp++)
            s_u[wid][q][cp][4 * p + r] = uc[r * 4 + cp];
    __syncwarp();

    // ---- Phase C: per row qq, out[o,c] = sum_er u[er,c]*Wrr[er,o] ----
    const float* wrb = g_wrr2 + lane * 4;
    #pragma unroll 1
    for (int qq = 0; qq < 4; qq++) {
        unsigned long long a3[16];   // [oi][cp]
        #pragma unroll
        for (int k = 0; k < 16; k++) a3[k] = 0ull;
        const unsigned long long* ub = &s_u[wid][qq][0][0];

        #pragma unroll 2
        for (int er2 = 0; er2 < 16; er2++) {
            ulonglong2 U0 = *(const ulonglong2*)(ub + 0*34 + er2*2);  // broadcast, 1 phase
            ulonglong2 U1 = *(const ulonglong2*)(ub + 1*34 + er2*2);
            ulonglong2 U2 = *(const ulonglong2*)(ub + 2*34 + er2*2);
            ulonglong2 U3 = *(const ulonglong2*)(ub + 3*34 + er2*2);
            float4 wa = *(const float4*)(wrb + (er2*2 + 0) * 128);    // coalesced, L1-hit
            float4 wb = *(const float4*)(wrb + (er2*2 + 1) * 128);
            unsigned long long wd;
            // er even
            wd = pack2(wa.x, wa.x); fma2(a3[0],wd,U0.x); fma2(a3[1],wd,U1.x); fma2(a3[2],wd,U2.x); fma2(a3[3],wd,U3.x);
            wd = pack2(wa.y, wa.y); fma2(a3[4],wd,U0.x); fma2(a3[5],wd,U1.x); fma2(a3[6],wd,U2.x); fma2(a3[7],wd,U3.x);
            wd = pack2(wa.z, wa.z); fma2(a3[8],wd,U0.x); fma2(a3[9],wd,U1.x); fma2(a3[10],wd,U2.x); fma2(a3[11],wd,U3.x);
            wd = pack2(wa.w, wa.w); fma2(a3[12],wd,U0.x); fma2(a3[13],wd,U1.x); fma2(a3[14],wd,U2.x); fma2(a3[15],wd,U3.x);
            // er odd
            wd = pack2(wb.x, wb.x); fma2(a3[0],wd,U0.y); fma2(a3[1],wd,U1.y); fma2(a3[2],wd,U2.y); fma2(a3[3],wd,U3.y);
            wd = pack2(wb.y, wb.y); fma2(a3[4],wd,U0.y); fma2(a3[5],wd,U1.y); fma2(a3[6],wd,U2.y); fma2(a3[7],wd,U3.y);
            wd = pack2(wb.z, wb.z); fma2(a3[8],wd,U0.y); fma2(a3[9],wd,U1.y); fma2(a3[10],wd,U2.y); fma2(a3[11],wd,U3.y);
            wd = pack2(wb.w, wb.w); fma2(a3[12],wd,U0.y); fma2(a3[13],wd,U1.y); fma2(a3[14],wd,U2.y); fma2(a3[15],wd,U3.y);
        }

        if (row0 + qq < nrows) {
            float* og = out + (size_t)(row0 + qq) * OUTDIM;
            #pragma unroll
            for (int oi = 0; oi < 4; oi++) {
                int o = lane + oi * 32;
                ulonglong2 v0; v0.x = a3[oi*4+0]; v0.y = a3[oi*4+1];
                ulonglong2 v1; v1.x = a3[oi*4+2]; v1.y = a3[oi*4+3];
                *(ulonglong2*)(og + o * 8)     = v0;
                *(ulonglong2*)(og + o * 8 + 4) = v1;
            }
        }
    }
}

extern "C" void kernel_launch(void* const* d_in, const int* in_sizes, int n_in,
                              void* d_out, int out_size) {
    const float* x   = (const float*)d_in[0];
    const float* wrl = (const float*)d_in[1];
    const float* wrr = (const float*)d_in[2];
    const float* wlf = (const float*)d_in[3];
    float* out = (float*)d_out;

    int nrows = in_sizes[0] / INDIM;               // B*S = 8192
    phm_prep<<<16, 256>>>(wrr);
    int grid = (nrows + 15) / 16;                  // 16 rows per block (4 warps x 4 rows)
    phm_main<<<grid, 128>>>(x, wrl, wlf, out, nrows);
}

// round 6
// speedup vs baseline: 1.2304x; 1.0028x over previous
#include <cuda_runtime.h>
#include <cstdint>
#include <cstddef>

#define INDIM 1024
#define OUTDIM 1024

// Packed Wrr: g_wrr2[er*128 + lane*4 + oi] = wrr[er*128 + oi*32 + lane]
__device__ float g_wrr2[32 * 128];

__global__ void phm_prep(const float* __restrict__ wrr) {
    int idx = blockIdx.x * blockDim.x + threadIdx.x;
    if (idx < 4096) {
        int er = idx >> 7, t = idx & 127;
        int l = t >> 2, oi = t & 3;
        g_wrr2[idx] = wrr[er * 128 + oi * 32 + l];
    }
}

__device__ __forceinline__ unsigned long long pack2(float lo, float hi) {
    unsigned long long r;
    asm("mov.b64 %0, {%1, %2};" : "=l"(r) : "f"(lo), "f"(hi));
    return r;
}
__device__ __forceinline__ void unpack2(unsigned long long v, float &lo, float &hi) {
    asm("mov.b64 {%0, %1}, %2;" : "=f"(lo), "=f"(hi) : "l"(v));
}
__device__ __forceinline__ void fma2(unsigned long long &d, unsigned long long a, unsigned long long b) {
    asm("fma.rn.f32x2 %0, %1, %2, %0;" : "+l"(d) : "l"(a), "l"(b));
}

__global__ void __launch_bounds__(128, 4)
phm_main(const float* __restrict__ x,
         const float* __restrict__ wrl,   // [8][128][4]
         const float* __restrict__ wlf,   // [8][8][8]
         float* __restrict__ out,
         int nrows)
{
    __shared__ __align__(16) float s_wrl2[8 * 516];              // [p][i4][r][j], p-stride 516
    __shared__ __align__(16) float s_wl[8 * 68];                 // [e][a*8+c], pad 68
    __shared__ __align__(16) unsigned long long s_u[4][4][4][34];// [warp][q][cp][er+pad]
    __shared__ __align__(16) float s_x[4][2][288];               // [warp][buf][2 slices of 144]

    const int tid  = threadIdx.x;
    const int lane = tid & 31;
    const int wid  = tid >> 5;
    const int q = lane >> 3;   // row within warp tile
    const int p = lane & 7;    // er quartet (== e); r = 0..3 within

    // ---- stage weights (once per block) ----
    #pragma unroll
    for (int k = 0; k < 32; k++) {
        int idx = tid + 128 * k;                  // 4096
        int pp = idx >> 9;
        int rem = idx & 511;
        int i = rem >> 2, r = rem & 3;
        s_wrl2[pp * 516 + (i >> 2) * 16 + r * 4 + (i & 3)] = wrl[idx];
    }
    #pragma unroll
    for (int k = 0; k < 4; k++) {
        int idx = tid + 128 * k;                  // 512
        s_wl[(idx >> 6) * 68 + (idx & 63)] = wlf[idx];
    }
    __syncthreads();

    int row0 = blockIdx.x * 16 + wid * 4;
    if (row0 >= nrows) return;

    // loader role: lane (q,p) loads row q, a = p, 16B per slice
    const float* xld = x + (size_t)min(row0 + q, nrows - 1) * INDIM + p * 128;
    float* sxw = &s_x[wid][0][0];
    const int sx_off = q * 36 + p * 4;

    // ---- Phase A: acc[a][r] packed over i-parity ----
    unsigned long long acc[32];
    #pragma unroll
    for (int k = 0; k < 32; k++) acc[k] = 0ull;

    {   // prologue: slices 0,1 -> buf0
        float4 t0 = *(const float4*)(xld);
        float4 t1 = *(const float4*)(xld + 4);
        *(float4*)(sxw + sx_off)       = t0;
        *(float4*)(sxw + 144 + sx_off) = t1;
    }
    float4 xq0 = *(const float4*)(xld + 8);    // slice 2
    float4 xq1 = *(const float4*)(xld + 12);   // slice 3

    const float* wvb = s_wrl2 + p * 516;
    const float* sxr = &s_x[wid][0][0] + q * 36;

    #pragma unroll 1
    for (int i8 = 0; i8 < 16; i8++) {
        __syncwarp();     // prev round's reads done; this round's buffer visible
        if (i8 < 15) {
            // store slices {2*i8+2, 2*i8+3} (loaded last iter) into the other buffer
            float* wb = sxw + ((i8 + 1) & 1) * 288 + sx_off;
            *(float4*)(wb)       = xq0;
            *(float4*)(wb + 144) = xq1;
            // load the NEXT pair {2*i8+4, 2*i8+5}
            int nxt = i8 * 2 + 4;
            xq0 = *(const float4*)(xld + min(nxt, 31) * 4);
            xq1 = *(const float4*)(xld + min(nxt + 1, 31) * 4);
        }
        const float* xb = sxr + (i8 & 1) * 288;
        #pragma unroll
        for (int half = 0; half < 2; half++) {
            const int i4 = i8 * 2 + half;
            ulonglong2 wv0 = *(const ulonglong2*)(wvb + i4 * 16);
            ulonglong2 wv1 = *(const ulonglong2*)(wvb + i4 * 16 + 4);
            ulonglong2 wv2 = *(const ulonglong2*)(wvb + i4 * 16 + 8);
            ulonglong2 wv3 = *(const ulonglong2*)(wvb + i4 * 16 + 12);
            const float* xh = xb + half * 144;
            #pragma unroll
            for (int a = 0; a < 8; a++) {
                ulonglong2 xv = *(const ulonglong2*)(xh + a * 4);   // 1 phase, 4 rows served
                fma2(acc[a*4+0], xv.x, wv0.x); fma2(acc[a*4+0], xv.y, wv0.y);
                fma2(acc[a*4+1], xv.x, wv1.x); fma2(acc[a*4+1], xv.y, wv1.y);
                fma2(acc[a*4+2], xv.x, wv2.x); fma2(acc[a*4+2], xv.y, wv2.y);
                fma2(acc[a*4+3], xv.x, wv3.x); fma2(acc[a*4+3], xv.y, wv3.y);
            }
        }
    }

    // ---- Phase B: u[r][cp] = sum_a y1[a][r] * Wl[p][a][c] (all in-lane) ----
    unsigned long long uc[16];
    #pragma unroll
    for (int k = 0; k < 16; k++) uc[k] = 0ull;
    const float* wlb = s_wl + p * 68;
    #pragma unroll
    for (int a = 0; a < 8; a++) {
        ulonglong2 W01 = *(const ulonglong2*)(wlb + a * 8);
        ulonglong2 W23 = *(const ulonglong2*)(wlb + a * 8 + 4);
        #pragma unroll
        for (int r = 0; r < 4; r++) {
            float lo, hi; unpack2(acc[a*4+r], lo, hi);
            float y = lo + hi;
            unsigned long long yd = pack2(y, y);
            fma2(uc[r*4+0], yd, W01.x);
            fma2(uc[r*4+1], yd, W01.y);
            fma2(uc[r*4+2], yd, W23.x);
            fma2(uc[r*4+3], yd, W23.y);
        }
    }
    #pragma unroll
    for (int r = 0; r < 4; r++)
        #pragma unroll
        for (int cp = 0; cp < 4; cp++)
            s_u[wid][q][cp][4 * p + r] = uc[r * 4 + cp];
    __syncwarp();

    // ---- Phase C: er outer, 2 rows inner; w + splats reused across rows ----
    const float* wrb = g_wrr2 + lane * 4;
    #pragma unroll 1
    for (int pass = 0; pass < 2; pass++) {
        const int qa = pass * 2;
        unsigned long long A0[16], A1[16];     // [oi][cp] for rows qa, qa+1
        #pragma unroll
        for (int k = 0; k < 16; k++) { A0[k] = 0ull; A1[k] = 0ull; }
        const unsigned long long* u0 = &s_u[wid][qa][0][0];
        const unsigned long long* u1 = &s_u[wid][qa + 1][0][0];

        #pragma unroll 2
        for (int er2 = 0; er2 < 16; er2++) {
            float4 wa = *(const float4*)(wrb + (er2 * 2 + 0) * 128);   // er even, L1-hit
            float4 wc = *(const float4*)(wrb + (er2 * 2 + 1) * 128);   // er odd
            unsigned long long we0 = pack2(wa.x, wa.x);
            unsigned long long we1 = pack2(wa.y, wa.y);
            unsigned long long we2 = pack2(wa.z, wa.z);
            unsigned long long we3 = pack2(wa.w, wa.w);
            unsigned long long wo0 = pack2(wc.x, wc.x);
            unsigned long long wo1 = pack2(wc.y, wc.y);
            unsigned long long wo2 = pack2(wc.z, wc.z);
            unsigned long long wo3 = pack2(wc.w, wc.w);

            // row qa
            ulonglong2 Ua0 = *(const ulonglong2*)(u0 + 0 * 34 + er2 * 2);  // broadcast, 1 phase
            ulonglong2 Ua1 = *(const ulonglong2*)(u0 + 1 * 34 + er2 * 2);
            ulonglong2 Ua2 = *(const ulonglong2*)(u0 + 2 * 34 + er2 * 2);
            ulonglong2 Ua3 = *(const ulonglong2*)(u0 + 3 * 34 + er2 * 2);
            fma2(A0[ 0], we0, Ua0.x); fma2(A0[ 1], we0, Ua1.x); fma2(A0[ 2], we0, Ua2.x); fma2(A0[ 3], we0, Ua3.x);
            fma2(A0[ 4], we1, Ua0.x); fma2(A0[ 5], we1, Ua1.x); fma2(A0[ 6], we1, Ua2.x); fma2(A0[ 7], we1, Ua3.x);
            fma2(A0[ 8], we2, Ua0.x); fma2(A0[ 9], we2, Ua1.x); fma2(A0[10], we2, Ua2.x); fma2(A0[11], we2, Ua3.x);
            fma2(A0[12], we3, Ua0.x); fma2(A0[13], we3, Ua1.x); fma2(A0[14], we3, Ua2.x); fma2(A0[15], we3, Ua3.x);
            fma2(A0[ 0], wo0, Ua0.y); fma2(A0[ 1], wo0, Ua1.y); fma2(A0[ 2], wo0, Ua2.y); fma2(A0[ 3], wo0, Ua3.y);
            fma2(A0[ 4], wo1, Ua0.y); fma2(A0[ 5], wo1, Ua1.y); fma2(A0[ 6], wo1, Ua2.y); fma2(A0[ 7], wo1, Ua3.y);
            fma2(A0[ 8], wo2, Ua0.y); fma2(A0[ 9], wo2, Ua1.y); fma2(A0[10], wo2, Ua2.y); fma2(A0[11], wo2, Ua3.y);
            fma2(A0[12], wo3, Ua0.y); fma2(A0[13], wo3, Ua1.y); fma2(A0[14], wo3, Ua2.y); fma2(A0[15], wo3, Ua3.y);

            // row qa+1 (reuses w splats)
            ulonglong2 Ub0 = *(const ulonglong2*)(u1 + 0 * 34 + er2 * 2);
            ulonglong2 Ub1 = *(const ulonglong2*)(u1 + 1 * 34 + er2 * 2);
            ulonglong2 Ub2 = *(const ulonglong2*)(u1 + 2 * 34 + er2 * 2);
            ulonglong2 Ub3 = *(const ulonglong2*)(u1 + 3 * 34 + er2 * 2);
            fma2(A1[ 0], we0, Ub0.x); fma2(A1[ 1], we0, Ub1.x); fma2(A1[ 2], we0, Ub2.x); fma2(A1[ 3], we0, Ub3.x);
            fma2(A1[ 4], we1, Ub0.x); fma2(A1[ 5], we1, Ub1.x); fma2(A1[ 6], we1, Ub2.x); fma2(A1[ 7], we1, Ub3.x);
            fma2(A1[ 8], we2, Ub0.x); fma2(A1[ 9], we2, Ub1.x); fma2(A1[10], we2, Ub2.x); fma2(A1[11], we2, Ub3.x);
            fma2(A1[12], we3, Ub0.x); fma2(A1[13], we3, Ub1.x); fma2(A1[14], we3, Ub2.x); fma2(A1[15], we3, Ub3.x);
            fma2(A1[ 0], wo0, Ub0.y); fma2(A1[ 1], wo0, Ub1.y); fma2(A1[ 2], wo0, Ub2.y); fma2(A1[ 3], wo0, Ub3.y);
            fma2(A1[ 4], wo1, Ub0.y); fma2(A1[ 5], wo1, Ub1.y); fma2(A1[ 6], wo1, Ub2.y); fma2(A1[ 7], wo1, Ub3.y);
            fma2(A1[ 8], wo2, Ub0.y); fma2(A1[ 9], wo2, Ub1.y); fma2(A1[10], wo2, Ub2.y); fma2(A1[11], wo2, Ub3.y);
            fma2(A1[12], wo3, Ub0.y); fma2(A1[13], wo3, Ub1.y); fma2(A1[14], wo3, Ub2.y); fma2(A1[15], wo3, Ub3.y);
        }

        if (row0 + qa < nrows) {
            float* og = out + (size_t)(row0 + qa) * OUTDIM;
            #pragma unroll
            for (int oi = 0; oi < 4; oi++) {
                int o = lane + oi * 32;
                ulonglong2 v0; v0.x = A0[oi*4+0]; v0.y = A0[oi*4+1];
                ulonglong2 v1; v1.x = A0[oi*4+2]; v1.y = A0[oi*4+3];
                *(ulonglong2*)(og + o * 8)     = v0;
                *(ulonglong2*)(og + o * 8 + 4) = v1;
            }
        }
        if (row0 + qa + 1 < nrows) {
            float* og = out + (size_t)(row0 + qa + 1) * OUTDIM;
            #pragma unroll
            for (int oi = 0; oi < 4; oi++) {
                int o = lane + oi * 32;
                ulonglong2 v0; v0.x = A1[oi*4+0]; v0.y = A1[oi*4+1];
                ulonglong2 v1; v1.x = A1[oi*4+2]; v1.y = A1[oi*4+3];
                *(ulonglong2*)(og + o * 8)     = v0;
                *(ulonglong2*)(og + o * 8 + 4) = v1;
            }
        }
    }
}

extern "C" void kernel_launch(void* const* d_in, const int* in_sizes, int n_in,
                              void* d_out, int out_size) {
    const float* x   = (const float*)d_in[0];
    const float* wrl = (const float*)d_in[1];
    const float* wrr = (const float*)d_in[2];
    const float* wlf = (const float*)d_in[3];
    float* out = (float*)d_out;

    int nrows = in_sizes[0] / INDIM;               // B*S = 8192
    phm_prep<<<16, 256>>>(wrr);
    int grid = (nrows + 15) / 16;                  // 16 rows per block (4 warps x 4 rows)
    phm_main<<<grid, 128>>>(x, wrl, wlf, out, nrows);
}